// round 1
// baseline (speedup 1.0000x reference)
#include <cuda_runtime.h>
#include <cuda_bf16.h>

// Problem constants
#define BB 4
#define LL 512
#define DD 256
#define HH 8
#define DH 32
#define NBUCK 12           // BUCKETS+1 rows in rel_table
#define QK_SCALE 0.17677669529663687f  // 1/sqrt(32)

// ---------------- device scratch (no allocation allowed) ----------------
__device__ float g_q[BB * HH * LL * DH];   // scaled q, (B,H,L,DH)
__device__ float g_k[BB * HH * LL * DH];
__device__ float g_v[BB * HH * LL * DH];
__device__ float g_ctx[BB * LL * DD];      // ctx in (B,L,D) layout
__device__ float g_P[BB * LL * NBUCK * HH];
__device__ int   g_mask_kind;              // 0=int32, 1=float32, 2=bytes

// ---------------- mask dtype detector ----------------
__global__ void detect_mask_kernel(const unsigned int* mw) {
    __shared__ int flags[2]; // [0]=saw float one, [1]=saw weird
    if (threadIdx.x < 2) flags[threadIdx.x] = 0;
    __syncthreads();
    int f1 = 0, f2 = 0;
    for (int i = threadIdx.x; i < 4096; i += blockDim.x) {
        unsigned int w = mw[i];
        if (w == 0u || w == 1u) continue;
        if (w == 0x3F800000u) { f1 = 1; continue; }
        f2 = 1;
    }
    if (f1) atomicOr(&flags[0], 1);
    if (f2) atomicOr(&flags[1], 1);
    __syncthreads();
    if (threadIdx.x == 0)
        g_mask_kind = flags[1] ? 2 : (flags[0] ? 1 : 0);
}

__device__ __forceinline__ int mask_at(const void* mask, int kind, int idx) {
    if (kind == 2) return ((const unsigned char*)mask)[idx] != 0;
    if (kind == 1) return ((const float*)mask)[idx] != 0.0f;
    return ((const int*)mask)[idx] != 0;
}

// ---------------- kernel 1: fused QKV projection GEMM ----------------
// C(2048x256) = X(2048x256) @ W(256x256) + bias, write permuted to (B,H,L,DH)
// z=0 -> Q (scaled), z=1 -> K, z=2 -> V
__global__ void qkv_gemm_kernel(const float* __restrict__ X,
                                const float* __restrict__ Wq, const float* __restrict__ bq,
                                const float* __restrict__ Wk, const float* __restrict__ bk,
                                const float* __restrict__ Wv, const float* __restrict__ bv) {
    const int z = blockIdx.z;
    const float* W    = (z == 0) ? Wq : (z == 1 ? Wk : Wv);
    const float* bias = (z == 0) ? bq : (z == 1 ? bk : bv);
    float* out        = (z == 0) ? g_q : (z == 1 ? g_k : g_v);
    const float scale = (z == 0) ? QK_SCALE : 1.0f;

    __shared__ float As[64][33];
    __shared__ float Bs[32][65];

    const int t = threadIdx.x;                 // 256 threads
    const int tr = (t >> 4) * 4;               // 0..60
    const int tc = (t & 15) * 4;               // 0..60
    const int rowBase = blockIdx.y * 64;
    const int colBase = blockIdx.x * 64;

    float acc[4][4];
#pragma unroll
    for (int i = 0; i < 4; i++)
#pragma unroll
        for (int j = 0; j < 4; j++) acc[i][j] = 0.0f;

    for (int k0 = 0; k0 < DD; k0 += 32) {
        for (int i = t; i < 64 * 32; i += 256) {
            int r = i >> 5, c = i & 31;
            As[r][c] = X[(rowBase + r) * DD + k0 + c];
        }
        for (int i = t; i < 32 * 64; i += 256) {
            int r = i >> 6, c = i & 63;
            Bs[r][c] = W[(k0 + r) * DD + colBase + c];
        }
        __syncthreads();
#pragma unroll
        for (int kk = 0; kk < 32; kk++) {
            float a[4], b[4];
#pragma unroll
            for (int i = 0; i < 4; i++) a[i] = As[tr + i][kk];
#pragma unroll
            for (int j = 0; j < 4; j++) b[j] = Bs[kk][tc + j];
#pragma unroll
            for (int i = 0; i < 4; i++)
#pragma unroll
                for (int j = 0; j < 4; j++) acc[i][j] = fmaf(a[i], b[j], acc[i][j]);
        }
        __syncthreads();
    }

#pragma unroll
    for (int i = 0; i < 4; i++) {
        int row = rowBase + tr + i;            // b*L + l
        int b = row >> 9, l = row & 511;
#pragma unroll
        for (int j = 0; j < 4; j++) {
            int col = colBase + tc + j;        // h*DH + d
            int h = col >> 5, d = col & 31;
            float val = (acc[i][j] + bias[col]) * scale;
            out[(((b * HH + h) * LL) + l) * DH + d] = val;
        }
    }
}

// ---------------- kernel 2: P precompute ----------------
// P[b,l,bucket,h] = sum_d (q[b,h,l,d] + v[h*32+d]) * rel_table[bucket, h*32+d]
__global__ void compute_P_kernel(const float* __restrict__ vvec,
                                 const float* __restrict__ rel_table) {
    __shared__ float qrow[DD];
    __shared__ float rel_s[NBUCK * DD];
    const int bl = blockIdx.x;                 // b*L + l
    const int b = bl >> 9, l = bl & 511;
    const int t = threadIdx.x;                 // 128 threads

    for (int i = t; i < DD; i += 128) {
        int h = i >> 5, d = i & 31;
        qrow[i] = g_q[(((b * HH + h) * LL) + l) * DH + d] + vvec[i];
    }
    for (int i = t; i < NBUCK * DD; i += 128) rel_s[i] = rel_table[i];
    __syncthreads();

    if (t < NBUCK * HH) {
        int bucket = t >> 3, h = t & 7;
        const float* rp = &rel_s[bucket * DD + h * DH];
        const float* qp = &qrow[h * DH];
        float s = 0.0f;
#pragma unroll
        for (int d = 0; d < DH; d++) s = fmaf(qp[d], rp[d], s);
        g_P[bl * (NBUCK * HH) + bucket * HH + h] = s;
    }
}

// ---------------- kernel 3: scores = (q+u) k^T + P[dist] , masked ----------------
// grid: (L/64 qtiles, B*H), block 256. Writes raw scores into attn buffer.
__global__ void scores_kernel(const float* __restrict__ uvec,
                              const void* __restrict__ mask,
                              const int* __restrict__ distances,
                              float* __restrict__ attn) {
    const int bh = blockIdx.y;                 // b*H + h
    const int b = bh >> 3, h = bh & 7;
    const int q0 = blockIdx.x * 64;
    const int t = threadIdx.x;
    const int kind = g_mask_kind;

    __shared__ float qu_s[64][33];
    __shared__ float Ks[128][33];

    for (int i = t; i < 64 * 32; i += 256) {
        int q = i >> 5, d = i & 31;
        qu_s[q][d] = g_q[((bh * LL) + (q0 + q)) * DH + d] + uvec[h * DH + d];
    }

    const int tq = (t >> 4) * 4;
    const int tk = (t & 15) * 8;

    for (int kc = 0; kc < LL; kc += 128) {
        __syncthreads();
        for (int i = t; i < 128 * 32; i += 256) {
            int k = i >> 5, d = i & 31;
            Ks[k][d] = g_k[((bh * LL) + (kc + k)) * DH + d];
        }
        __syncthreads();

        float acc[4][8];
#pragma unroll
        for (int i = 0; i < 4; i++)
#pragma unroll
            for (int j = 0; j < 8; j++) acc[i][j] = 0.0f;

#pragma unroll
        for (int d = 0; d < DH; d++) {
            float a[4], bb[8];
#pragma unroll
            for (int i = 0; i < 4; i++) a[i] = qu_s[tq + i][d];
#pragma unroll
            for (int j = 0; j < 8; j++) bb[j] = Ks[tk + j][d];
#pragma unroll
            for (int i = 0; i < 4; i++)
#pragma unroll
                for (int j = 0; j < 8; j++) acc[i][j] = fmaf(a[i], bb[j], acc[i][j]);
        }

#pragma unroll
        for (int i = 0; i < 4; i++) {
            int q = q0 + tq + i;
            int rowbase = (b * LL + q) * LL;              // index into (B,Lq,Lk)
            const float* Pq = &g_P[(b * LL + q) * (NBUCK * HH)];
            float* arow = attn + ((long)(bh * LL + q)) * LL;
#pragma unroll
            for (int j = 0; j < 8; j++) {
                int k = kc + tk + j;
                int dist = distances[rowbase + k];
                int m = mask_at(mask, kind, rowbase + k);
                float sc = m ? -1e18f : (acc[i][j] + Pq[dist * HH + h]);
                arow[k] = sc;
            }
        }
    }
}

// ---------------- kernel 4: row softmax in place ----------------
__global__ void softmax_kernel(float* __restrict__ attn) {
    float* p = attn + (long)blockIdx.x * LL;
    const int t = threadIdx.x;                 // 256 threads, 2 elems each
    float v0 = p[t], v1 = p[t + 256];

    __shared__ float redm[8];
    __shared__ float reds[8];

    float m = fmaxf(v0, v1);
#pragma unroll
    for (int o = 16; o; o >>= 1) m = fmaxf(m, __shfl_xor_sync(0xffffffffu, m, o));
    if ((t & 31) == 0) redm[t >> 5] = m;
    __syncthreads();
    if (t == 0) {
        float mm = redm[0];
#pragma unroll
        for (int i = 1; i < 8; i++) mm = fmaxf(mm, redm[i]);
        redm[0] = mm;
    }
    __syncthreads();
    const float rowmax = redm[0];

    float e0 = __expf(v0 - rowmax);
    float e1 = __expf(v1 - rowmax);
    float s = e0 + e1;
#pragma unroll
    for (int o = 16; o; o >>= 1) s += __shfl_xor_sync(0xffffffffu, s, o);
    if ((t & 31) == 0) reds[t >> 5] = s;
    __syncthreads();
    if (t == 0) {
        float ss = reds[0];
#pragma unroll
        for (int i = 1; i < 8; i++) ss += reds[i];
        reds[0] = ss;
    }
    __syncthreads();
    const float inv = 1.0f / reds[0];

    p[t]       = e0 * inv;
    p[t + 256] = e1 * inv;
}

// ---------------- kernel 5: ctx = attn @ V per (b,h), write (B,L,D) ----------------
__global__ void ctx_kernel(const float* __restrict__ attn) {
    const int bh = blockIdx.y;
    const int b = bh >> 3, h = bh & 7;
    const int q0 = blockIdx.x * 64;
    const int t = threadIdx.x;

    __shared__ float As[64][65];
    __shared__ float Vs[64][33];

    const int tq = (t >> 3) * 2;               // 0..62
    const int td = (t & 7) * 4;                // 0..28

    float acc[2][4];
#pragma unroll
    for (int i = 0; i < 2; i++)
#pragma unroll
        for (int j = 0; j < 4; j++) acc[i][j] = 0.0f;

    for (int kc = 0; kc < LL; kc += 64) {
        for (int i = t; i < 64 * 64; i += 256) {
            int q = i >> 6, k = i & 63;
            As[q][k] = attn[((long)(bh * LL + q0 + q)) * LL + kc + k];
        }
        for (int i = t; i < 64 * 32; i += 256) {
            int k = i >> 5, d = i & 31;
            Vs[k][d] = g_v[((bh * LL) + (kc + k)) * DH + d];
        }
        __syncthreads();
#pragma unroll 8
        for (int kk = 0; kk < 64; kk++) {
            float a0 = As[tq][kk], a1 = As[tq + 1][kk];
            float vv[4];
#pragma unroll
            for (int j = 0; j < 4; j++) vv[j] = Vs[kk][td + j];
#pragma unroll
            for (int j = 0; j < 4; j++) {
                acc[0][j] = fmaf(a0, vv[j], acc[0][j]);
                acc[1][j] = fmaf(a1, vv[j], acc[1][j]);
            }
        }
        __syncthreads();
    }

#pragma unroll
    for (int i = 0; i < 2; i++) {
        int q = q0 + tq + i;
#pragma unroll
        for (int j = 0; j < 4; j++) {
            g_ctx[(b * LL + q) * DD + h * DH + td + j] = acc[i][j];
        }
    }
}

// ---------------- kernel 6: output GEMM ctx @ Wo + bo ----------------
__global__ void out_gemm_kernel(const float* __restrict__ Wo,
                                const float* __restrict__ bo,
                                float* __restrict__ out) {
    __shared__ float As[64][33];
    __shared__ float Bs[32][65];

    const int t = threadIdx.x;
    const int tr = (t >> 4) * 4;
    const int tc = (t & 15) * 4;
    const int rowBase = blockIdx.y * 64;
    const int colBase = blockIdx.x * 64;

    float acc[4][4];
#pragma unroll
    for (int i = 0; i < 4; i++)
#pragma unroll
        for (int j = 0; j < 4; j++) acc[i][j] = 0.0f;

    for (int k0 = 0; k0 < DD; k0 += 32) {
        for (int i = t; i < 64 * 32; i += 256) {
            int r = i >> 5, c = i & 31;
            As[r][c] = g_ctx[(rowBase + r) * DD + k0 + c];
        }
        for (int i = t; i < 32 * 64; i += 256) {
            int r = i >> 6, c = i & 63;
            Bs[r][c] = Wo[(k0 + r) * DD + colBase + c];
        }
        __syncthreads();
#pragma unroll
        for (int kk = 0; kk < 32; kk++) {
            float a[4], b[4];
#pragma unroll
            for (int i = 0; i < 4; i++) a[i] = As[tr + i][kk];
#pragma unroll
            for (int j = 0; j < 4; j++) b[j] = Bs[kk][tc + j];
#pragma unroll
            for (int i = 0; i < 4; i++)
#pragma unroll
                for (int j = 0; j < 4; j++) acc[i][j] = fmaf(a[i], b[j], acc[i][j]);
        }
        __syncthreads();
    }

#pragma unroll
    for (int i = 0; i < 4; i++) {
        int row = rowBase + tr + i;
#pragma unroll
        for (int j = 0; j < 4; j++) {
            int col = colBase + tc + j;
            out[row * DD + col] = acc[i][j] + bo[col];
        }
    }
}

// ---------------- launch ----------------
extern "C" void kernel_launch(void* const* d_in, const int* in_sizes, int n_in,
                              void* d_out, int out_size) {
    const float* X         = (const float*)d_in[0];
    const void*  mask      = d_in[1];
    const int*   distances = (const int*)d_in[2];
    const float* Wq        = (const float*)d_in[3];
    const float* bq        = (const float*)d_in[4];
    const float* Wk        = (const float*)d_in[5];
    const float* bk        = (const float*)d_in[6];
    const float* Wv        = (const float*)d_in[7];
    const float* bv        = (const float*)d_in[8];
    const float* Wo        = (const float*)d_in[9];
    const float* bo        = (const float*)d_in[10];
    const float* rel_table = (const float*)d_in[11];
    const float* uvec      = (const float*)d_in[12];
    const float* vvec      = (const float*)d_in[13];

    float* out  = (float*)d_out;                       // (B,L,D)
    float* attn = (float*)d_out + BB * LL * DD;        // (B,H,L,L)

    detect_mask_kernel<<<1, 256>>>((const unsigned int*)mask);
    qkv_gemm_kernel<<<dim3(4, 32, 3), 256>>>(X, Wq, bq, Wk, bk, Wv, bv);
    compute_P_kernel<<<BB * LL, 128>>>(vvec, rel_table);
    scores_kernel<<<dim3(LL / 64, BB * HH), 256>>>(uvec, mask, distances, attn);
    softmax_kernel<<<BB * HH * LL, 256>>>(attn);
    ctx_kernel<<<dim3(LL / 64, BB * HH), 256>>>(attn);
    out_gemm_kernel<<<dim3(4, 32), 256>>>(Wo, bo, out);
}

// round 2
// speedup vs baseline: 1.3502x; 1.3502x over previous
#include <cuda_runtime.h>
#include <cuda_bf16.h>

// Problem constants
#define BB 4
#define LL 512
#define DD 256
#define HH 8
#define DH 32
#define QK_SCALE 0.17677669529663687f  // 1/sqrt(32)

// ---------------- device scratch ----------------
__device__ float g_q[BB * HH * LL * DH];   // scaled q, (B,H,L,DH)
__device__ float g_k[BB * HH * LL * DH];
__device__ float g_v[BB * HH * LL * DH];
__device__ float g_ctx[BB * LL * DD];      // ctx in (B,L,D) layout
__device__ float g_P[BB * LL * HH * 16];   // [b*L+l][h][bucket(16, 12=-1e18)]
__device__ unsigned char g_idx[BB * LL * LL]; // fused mask+distance bucket index
__device__ int   g_mask_kind;              // 0=int32, 1=float32, 2=bytes

// ---------------- mask dtype detector ----------------
__global__ void detect_mask_kernel(const unsigned int* mw) {
    __shared__ int flags[2];
    if (threadIdx.x < 2) flags[threadIdx.x] = 0;
    __syncthreads();
    int f1 = 0, f2 = 0;
    for (int i = threadIdx.x; i < 4096; i += blockDim.x) {
        unsigned int w = mw[i];
        if (w == 0u || w == 1u) continue;
        if (w == 0x3F800000u) { f1 = 1; continue; }
        f2 = 1;
    }
    if (f1) atomicOr(&flags[0], 1);
    if (f2) atomicOr(&flags[1], 1);
    __syncthreads();
    if (threadIdx.x == 0)
        g_mask_kind = flags[1] ? 2 : (flags[0] ? 1 : 0);
}

// ---------------- prep: idx = mask ? 12 : dist (bytes) ----------------
__global__ void prep_idx_kernel(const void* __restrict__ mask,
                                const int* __restrict__ dist) {
    const int kind = g_mask_kind;
    const int i = blockIdx.x * 256 + threadIdx.x;      // over 1M/4
    int4 d4 = ((const int4*)dist)[i];
    int m0, m1, m2, m3;
    if (kind == 2) {
        uchar4 m = ((const uchar4*)mask)[i];
        m0 = m.x; m1 = m.y; m2 = m.z; m3 = m.w;
    } else if (kind == 1) {
        float4 m = ((const float4*)mask)[i];
        m0 = (m.x != 0.0f); m1 = (m.y != 0.0f); m2 = (m.z != 0.0f); m3 = (m.w != 0.0f);
    } else {
        int4 m = ((const int4*)mask)[i];
        m0 = m.x; m1 = m.y; m2 = m.z; m3 = m.w;
    }
    uchar4 o;
    o.x = m0 ? 12 : (unsigned char)d4.x;
    o.y = m1 ? 12 : (unsigned char)d4.y;
    o.z = m2 ? 12 : (unsigned char)d4.z;
    o.w = m3 ? 12 : (unsigned char)d4.w;
    ((uchar4*)g_idx)[i] = o;
}

// ---------------- kernel 1: fused QKV projection GEMM ----------------
__global__ __launch_bounds__(256) void qkv_gemm_kernel(
        const float* __restrict__ X,
        const float* __restrict__ Wq, const float* __restrict__ bq,
        const float* __restrict__ Wk, const float* __restrict__ bk,
        const float* __restrict__ Wv, const float* __restrict__ bv) {
    const int z = blockIdx.z;
    const float* W    = (z == 0) ? Wq : (z == 1 ? Wk : Wv);
    const float* bias = (z == 0) ? bq : (z == 1 ? bk : bv);
    float* out        = (z == 0) ? g_q : (z == 1 ? g_k : g_v);
    const float scale = (z == 0) ? QK_SCALE : 1.0f;

    __shared__ float As[64 * 65];
    __shared__ float Bs[64 * 68];

    const int t = threadIdx.x;
    const int tr = (t >> 4) * 4;
    const int tc = (t & 15) * 4;
    const int rowBase = blockIdx.y * 64;
    const int colBase = blockIdx.x * 64;

    float acc[4][4];
#pragma unroll
    for (int i = 0; i < 4; i++)
#pragma unroll
        for (int j = 0; j < 4; j++) acc[i][j] = 0.0f;

    for (int k0 = 0; k0 < DD; k0 += 64) {
        {
            for (int i = t; i < 1024; i += 256) {
                int m = i >> 4, k4 = (i & 15) * 4;
                float4 x = *(const float4*)(X + (rowBase + m) * DD + k0 + k4);
                As[m * 65 + k4 + 0] = x.x;
                As[m * 65 + k4 + 1] = x.y;
                As[m * 65 + k4 + 2] = x.z;
                As[m * 65 + k4 + 3] = x.w;
            }
            for (int i = t; i < 1024; i += 256) {
                int k = i >> 4, n4 = (i & 15) * 4;
                float4 w = *(const float4*)(W + (k0 + k) * DD + colBase + n4);
                *(float4*)(Bs + k * 68 + n4) = w;
            }
        }
        __syncthreads();
#pragma unroll 16
        for (int kk = 0; kk < 64; kk++) {
            float a[4];
#pragma unroll
            for (int i = 0; i < 4; i++) a[i] = As[(tr + i) * 65 + kk];
            float4 b4 = *(const float4*)(Bs + kk * 68 + tc);
#pragma unroll
            for (int i = 0; i < 4; i++) {
                acc[i][0] = fmaf(a[i], b4.x, acc[i][0]);
                acc[i][1] = fmaf(a[i], b4.y, acc[i][1]);
                acc[i][2] = fmaf(a[i], b4.z, acc[i][2]);
                acc[i][3] = fmaf(a[i], b4.w, acc[i][3]);
            }
        }
        __syncthreads();
    }

    const int col0 = colBase + tc;
    const int h = col0 >> 5, d = col0 & 31;
    const float4 bi = *(const float4*)(bias + col0);
#pragma unroll
    for (int i = 0; i < 4; i++) {
        int row = rowBase + tr + i;
        int b = row >> 9, l = row & 511;
        float4 o;
        o.x = (acc[i][0] + bi.x) * scale;
        o.y = (acc[i][1] + bi.y) * scale;
        o.z = (acc[i][2] + bi.z) * scale;
        o.w = (acc[i][3] + bi.w) * scale;
        *(float4*)(out + (((b * HH + h) * LL) + l) * DH + d) = o;
    }
}

// ---------------- kernel 2: P precompute (13 buckets, padded to 16) ----------------
__global__ void compute_P_kernel(const float* __restrict__ vvec,
                                 const float* __restrict__ rel_table) {
    __shared__ float qrow[DD];
    __shared__ float rel_s[12 * DD];
    const int bl = blockIdx.x;
    const int b = bl >> 9, l = bl & 511;
    const int t = threadIdx.x;                 // 128 threads

    for (int i = t; i < DD; i += 128) {
        int h = i >> 5, d = i & 31;
        qrow[i] = g_q[(((b * HH + h) * LL) + l) * DH + d] + vvec[i];
    }
    for (int i = t; i < 12 * DD; i += 128) rel_s[i] = rel_table[i];
    __syncthreads();

    if (t < 96) {
        int h = t / 12, bucket = t % 12;
        const float* rp = &rel_s[bucket * DD + h * DH];
        const float* qp = &qrow[h * DH];
        float s = 0.0f;
#pragma unroll
        for (int d = 0; d < DH; d++) s = fmaf(qp[d], rp[d], s);
        g_P[(bl * HH + h) * 16 + bucket] = s;
    } else if (t < 104) {
        int h = t - 96;
        g_P[(bl * HH + h) * 16 + 12] = -1e18f;
    }
}

// ---------------- kernel 3: scores = (q+u) k^T + P[idx] ----------------
// 128 threads, tile 32q x 128k, grid ( (qt*4+kt), bh )
__global__ __launch_bounds__(128) void scores_kernel(
        const float* __restrict__ uvec,
        float* __restrict__ attn) {
    const int bh = blockIdx.y;
    const int b = bh >> 3, h = bh & 7;
    const int kt = blockIdx.x & 3;
    const int qt = blockIdx.x >> 2;
    const int q0 = qt * 32;
    const int k0 = kt * 128;
    const int t = threadIdx.x;

    __shared__ float qu_s[32 * 33];
    __shared__ float Ks[128 * 32];     // XOR-swizzled: [k*32 + (d ^ (2*((k>>3)&15)))]
    __shared__ float Ps_s[32 * 16];

    // load q+u tile
    for (int i = t; i < 256; i += 128) {
        int q = i >> 3, d4 = (i & 7) * 4;
        float4 qv = *(const float4*)(g_q + ((size_t)(bh * LL) + q0 + q) * DH + d4);
        float4 uv = *(const float4*)(uvec + h * DH + d4);
        qu_s[q * 33 + d4 + 0] = qv.x + uv.x;
        qu_s[q * 33 + d4 + 1] = qv.y + uv.y;
        qu_s[q * 33 + d4 + 2] = qv.z + uv.z;
        qu_s[q * 33 + d4 + 3] = qv.w + uv.w;
    }
    // load K tile with swizzle
    for (int i = t; i < 1024; i += 128) {
        int k = i >> 3, d4 = (i & 7) * 4;
        float4 kv = *(const float4*)(g_k + ((size_t)(bh * LL) + k0 + k) * DH + d4);
        int swz = ((k >> 3) & 15) << 1;
        Ks[k * 32 + ((d4 + 0) ^ swz)] = kv.x;
        Ks[k * 32 + ((d4 + 1) ^ swz)] = kv.y;
        Ks[k * 32 + ((d4 + 2) ^ swz)] = kv.z;
        Ks[k * 32 + ((d4 + 3) ^ swz)] = kv.w;
    }
    // load P tile: 32 q rows x 16
    {
        int q = t >> 2, s4 = (t & 3) * 4;
        *(float4*)(Ps_s + q * 16 + s4) =
            *(const float4*)(g_P + ((size_t)(b * LL + q0 + q) * HH + h) * 16 + s4);
    }
    __syncthreads();

    const int tq = (t >> 4) * 4;       // 0..28
    const int tk = (t & 15) * 8;       // 0..120
    const int dxor = (t & 15) << 1;    // swizzle for this thread's k-group

    float acc[4][8];
#pragma unroll
    for (int i = 0; i < 4; i++)
#pragma unroll
        for (int j = 0; j < 8; j++) acc[i][j] = 0.0f;

#pragma unroll
    for (int d = 0; d < DH; d++) {
        float a[4], bb[8];
#pragma unroll
        for (int i = 0; i < 4; i++) a[i] = qu_s[(tq + i) * 33 + d];
        int dsw = d ^ dxor;
#pragma unroll
        for (int j = 0; j < 8; j++) bb[j] = Ks[(tk + j) * 32 + dsw];
#pragma unroll
        for (int i = 0; i < 4; i++)
#pragma unroll
            for (int j = 0; j < 8; j++) acc[i][j] = fmaf(a[i], bb[j], acc[i][j]);
    }

    // epilogue: add P[idx] and store
#pragma unroll
    for (int i = 0; i < 4; i++) {
        int q = q0 + tq + i;
        uint2 u8 = *(const uint2*)(g_idx + ((size_t)(b * LL + q) * LL) + k0 + tk);
        const float* Pq = Ps_s + (tq + i) * 16;
        float4 o0, o1;
        o0.x = acc[i][0] + Pq[u8.x & 255];
        o0.y = acc[i][1] + Pq[(u8.x >> 8) & 255];
        o0.z = acc[i][2] + Pq[(u8.x >> 16) & 255];
        o0.w = acc[i][3] + Pq[(u8.x >> 24) & 255];
        o1.x = acc[i][4] + Pq[u8.y & 255];
        o1.y = acc[i][5] + Pq[(u8.y >> 8) & 255];
        o1.z = acc[i][6] + Pq[(u8.y >> 16) & 255];
        o1.w = acc[i][7] + Pq[(u8.y >> 24) & 255];
        float4* dst = (float4*)(attn + ((size_t)(bh * LL + q)) * LL + k0 + tk);
        dst[0] = o0;
        dst[1] = o1;
    }
}

// ---------------- kernel 4: fused softmax + attn-write + ctx ----------------
// block per (bh, qtile=32), 256 threads, dynamic smem
__global__ __launch_bounds__(256) void softctx_kernel(float* __restrict__ attn) {
    extern __shared__ float sm[];
    float* S    = sm;                   // [32][516]
    float* Vs   = sm + 32 * 516;        // [128][36]
    float* invp = Vs + 128 * 36;        // [32]

    const int bh = blockIdx.y;
    const int q0 = blockIdx.x * 32;
    const int t = threadIdx.x;
    float* arow = attn + ((size_t)(bh * LL + q0)) * LL;

    // load raw scores
    for (int i = t; i < 32 * 128; i += 256) {
        int r = i >> 7, c4 = (i & 127) << 2;
        float4 v = *(const float4*)(arow + r * LL + c4);
        *(float4*)(S + r * 516 + c4) = v;
    }
    __syncthreads();

    // per-row max / exp / sum  (warp w owns rows 4w..4w+3)
    {
        const int w = t >> 5, lane = t & 31;
#pragma unroll
        for (int rr = 0; rr < 4; rr++) {
            int r = w * 4 + rr;
            float* Sr = S + r * 516;
            float m = -3.4e38f;
            for (int c = lane; c < LL; c += 32) m = fmaxf(m, Sr[c]);
#pragma unroll
            for (int o = 16; o; o >>= 1) m = fmaxf(m, __shfl_xor_sync(0xffffffffu, m, o));
            float s = 0.0f;
            for (int c = lane; c < LL; c += 32) {
                float e = __expf(Sr[c] - m);
                Sr[c] = e;
                s += e;
            }
#pragma unroll
            for (int o = 16; o; o >>= 1) s += __shfl_xor_sync(0xffffffffu, s, o);
            if (lane == 0) invp[r] = 1.0f / s;
        }
    }
    __syncthreads();

    // write normalized attn
    for (int i = t; i < 32 * 128; i += 256) {
        int r = i >> 7, c4 = (i & 127) << 2;
        float iv = invp[r];
        float4 e = *(const float4*)(S + r * 516 + c4);
        float4 o = make_float4(e.x * iv, e.y * iv, e.z * iv, e.w * iv);
        *(float4*)(arow + r * LL + c4) = o;
    }

    // ctx GEMM: S(32x512) @ V(512x32), normalization folded at the end
    const int q = t >> 3;
    const int d4 = (t & 7) * 4;
    float4 acc = make_float4(0.f, 0.f, 0.f, 0.f);

    for (int kc = 0; kc < LL; kc += 128) {
        __syncthreads();
        for (int i = t; i < 1024; i += 256) {
            int k = i >> 3, dd = (i & 7) * 4;
            float4 vv = *(const float4*)(g_v + ((size_t)(bh * LL) + kc + k) * DH + dd);
            *(float4*)(Vs + k * 36 + dd) = vv;
        }
        __syncthreads();
        const float* Sq = S + q * 516 + kc;
#pragma unroll 4
        for (int kk = 0; kk < 128; kk++) {
            float a = Sq[kk];
            float4 b4 = *(const float4*)(Vs + kk * 36 + d4);
            acc.x = fmaf(a, b4.x, acc.x);
            acc.y = fmaf(a, b4.y, acc.y);
            acc.z = fmaf(a, b4.z, acc.z);
            acc.w = fmaf(a, b4.w, acc.w);
        }
    }
    const float iv = invp[q];
    const int b = bh >> 3, h = bh & 7;
    float4 o = make_float4(acc.x * iv, acc.y * iv, acc.z * iv, acc.w * iv);
    *(float4*)(g_ctx + ((size_t)(b * LL) + q0 + q) * DD + h * DH + d4) = o;
}

// ---------------- kernel 5: output GEMM ctx @ Wo + bo ----------------
__global__ __launch_bounds__(256) void out_gemm_kernel(
        const float* __restrict__ Wo,
        const float* __restrict__ bo,
        float* __restrict__ out) {
    __shared__ float As[64 * 65];
    __shared__ float Bs[64 * 68];

    const int t = threadIdx.x;
    const int tr = (t >> 4) * 4;
    const int tc = (t & 15) * 4;
    const int rowBase = blockIdx.y * 64;
    const int colBase = blockIdx.x * 64;

    float acc[4][4];
#pragma unroll
    for (int i = 0; i < 4; i++)
#pragma unroll
        for (int j = 0; j < 4; j++) acc[i][j] = 0.0f;

    for (int k0 = 0; k0 < DD; k0 += 64) {
        for (int i = t; i < 1024; i += 256) {
            int m = i >> 4, k4 = (i & 15) * 4;
            float4 x = *(const float4*)(g_ctx + (rowBase + m) * DD + k0 + k4);
            As[m * 65 + k4 + 0] = x.x;
            As[m * 65 + k4 + 1] = x.y;
            As[m * 65 + k4 + 2] = x.z;
            As[m * 65 + k4 + 3] = x.w;
        }
        for (int i = t; i < 1024; i += 256) {
            int k = i >> 4, n4 = (i & 15) * 4;
            float4 w = *(const float4*)(Wo + (k0 + k) * DD + colBase + n4);
            *(float4*)(Bs + k * 68 + n4) = w;
        }
        __syncthreads();
#pragma unroll 16
        for (int kk = 0; kk < 64; kk++) {
            float a[4];
#pragma unroll
            for (int i = 0; i < 4; i++) a[i] = As[(tr + i) * 65 + kk];
            float4 b4 = *(const float4*)(Bs + kk * 68 + tc);
#pragma unroll
            for (int i = 0; i < 4; i++) {
                acc[i][0] = fmaf(a[i], b4.x, acc[i][0]);
                acc[i][1] = fmaf(a[i], b4.y, acc[i][1]);
                acc[i][2] = fmaf(a[i], b4.z, acc[i][2]);
                acc[i][3] = fmaf(a[i], b4.w, acc[i][3]);
            }
        }
        __syncthreads();
    }

    const int col0 = colBase + tc;
    const float4 bi = *(const float4*)(bo + col0);
#pragma unroll
    for (int i = 0; i < 4; i++) {
        int row = rowBase + tr + i;
        float4 o;
        o.x = acc[i][0] + bi.x;
        o.y = acc[i][1] + bi.y;
        o.z = acc[i][2] + bi.z;
        o.w = acc[i][3] + bi.w;
        *(float4*)(out + row * DD + col0) = o;
    }
}

// ---------------- launch ----------------
extern "C" void kernel_launch(void* const* d_in, const int* in_sizes, int n_in,
                              void* d_out, int out_size) {
    const float* X         = (const float*)d_in[0];
    const void*  mask      = d_in[1];
    const int*   distances = (const int*)d_in[2];
    const float* Wq        = (const float*)d_in[3];
    const float* bq        = (const float*)d_in[4];
    const float* Wk        = (const float*)d_in[5];
    const float* bk        = (const float*)d_in[6];
    const float* Wv        = (const float*)d_in[7];
    const float* bv        = (const float*)d_in[8];
    const float* Wo        = (const float*)d_in[9];
    const float* bo        = (const float*)d_in[10];
    const float* rel_table = (const float*)d_in[11];
    const float* uvec      = (const float*)d_in[12];
    const float* vvec      = (const float*)d_in[13];

    float* out  = (float*)d_out;                       // (B,L,D)
    float* attn = (float*)d_out + BB * LL * DD;        // (B,H,L,L)

    static int smem_set = 0;
    const int softctx_smem = (32 * 516 + 128 * 36 + 32) * 4;
    if (!smem_set) {
        cudaFuncSetAttribute(softctx_kernel,
                             cudaFuncAttributeMaxDynamicSharedMemorySize,
                             softctx_smem);
        smem_set = 1;
    }

    detect_mask_kernel<<<1, 256>>>((const unsigned int*)mask);
    prep_idx_kernel<<<1024, 256>>>(mask, distances);
    qkv_gemm_kernel<<<dim3(4, 32, 3), 256>>>(X, Wq, bq, Wk, bk, Wv, bv);
    compute_P_kernel<<<BB * LL, 128>>>(vvec, rel_table);
    scores_kernel<<<dim3(64, 32), 128>>>(uvec, attn);
    softctx_kernel<<<dim3(16, 32), 256, softctx_smem>>>(attn);
    out_gemm_kernel<<<dim3(4, 32), 256>>>(Wo, bo, out);
}

// round 3
// speedup vs baseline: 1.5624x; 1.1572x over previous
#include <cuda_runtime.h>
#include <cuda_bf16.h>

// Problem constants
#define BB 4
#define LL 512
#define DD 256
#define HH 8
#define DH 32
#define QK_SCALE 0.17677669529663687f  // 1/sqrt(32)

typedef unsigned long long ull;

// ---------------- f32x2 packed-pair helpers (Blackwell FFMA2) ----------------
__device__ __forceinline__ ull pack2(float x, float y) {
    ull d; asm("mov.b64 %0, {%1, %2};" : "=l"(d) : "f"(x), "f"(y)); return d;
}
__device__ __forceinline__ float2 unpack2(ull v) {
    float2 r; asm("mov.b64 {%0, %1}, %2;" : "=f"(r.x), "=f"(r.y) : "l"(v)); return r;
}
__device__ __forceinline__ ull fma2(ull a, ull b, ull c) {
    ull d; asm("fma.rn.f32x2 %0, %1, %2, %3;" : "=l"(d) : "l"(a), "l"(b), "l"(c)); return d;
}

// ---------------- device scratch ----------------
__device__ float g_q[BB * HH * LL * DH];   // scaled q, (B,H,L,DH)
__device__ float g_k[BB * HH * LL * DH];
__device__ float g_v[BB * HH * LL * DH];
__device__ float g_ctx[BB * LL * DD];      // ctx in (B,L,D) layout
__device__ unsigned char g_idx[BB * LL * LL]; // fused mask+distance bucket index
__device__ int   g_mask_kind;              // 0=int32, 1=float32, 2=bytes

// ---------------- mask dtype detector ----------------
__global__ void detect_mask_kernel(const unsigned int* mw) {
    __shared__ int flags[2];
    if (threadIdx.x < 2) flags[threadIdx.x] = 0;
    __syncthreads();
    int f1 = 0, f2 = 0;
    for (int i = threadIdx.x; i < 4096; i += blockDim.x) {
        unsigned int w = mw[i];
        if (w == 0u || w == 1u) continue;
        if (w == 0x3F800000u) { f1 = 1; continue; }
        f2 = 1;
    }
    if (f1) atomicOr(&flags[0], 1);
    if (f2) atomicOr(&flags[1], 1);
    __syncthreads();
    if (threadIdx.x == 0)
        g_mask_kind = flags[1] ? 2 : (flags[0] ? 1 : 0);
}

// ---------------- prep: idx = mask ? 12 : dist (bytes) ----------------
__global__ void prep_idx_kernel(const void* __restrict__ mask,
                                const int* __restrict__ dist) {
    const int kind = g_mask_kind;
    const int i = blockIdx.x * 256 + threadIdx.x;      // over 1M/4
    int4 d4 = ((const int4*)dist)[i];
    int m0, m1, m2, m3;
    if (kind == 2) {
        uchar4 m = ((const uchar4*)mask)[i];
        m0 = m.x; m1 = m.y; m2 = m.z; m3 = m.w;
    } else if (kind == 1) {
        float4 m = ((const float4*)mask)[i];
        m0 = (m.x != 0.0f); m1 = (m.y != 0.0f); m2 = (m.z != 0.0f); m3 = (m.w != 0.0f);
    } else {
        int4 m = ((const int4*)mask)[i];
        m0 = m.x; m1 = m.y; m2 = m.z; m3 = m.w;
    }
    uchar4 o;
    o.x = m0 ? 12 : (unsigned char)d4.x;
    o.y = m1 ? 12 : (unsigned char)d4.y;
    o.z = m2 ? 12 : (unsigned char)d4.z;
    o.w = m3 ? 12 : (unsigned char)d4.w;
    ((uchar4*)g_idx)[i] = o;
}

// ---------------- kernel 1: fused QKV projection GEMM (f32x2) ----------------
// C(2048x256) = X @ W + bias, permuted writes. 64x64 tile, pairs over M rows.
__global__ __launch_bounds__(256) void qkv_gemm_kernel(
        const float* __restrict__ X,
        const float* __restrict__ Wq, const float* __restrict__ bq,
        const float* __restrict__ Wk, const float* __restrict__ bk,
        const float* __restrict__ Wv, const float* __restrict__ bv) {
    const int z = blockIdx.z;
    const float* W    = (z == 0) ? Wq : (z == 1 ? Wk : Wv);
    const float* bias = (z == 0) ? bq : (z == 1 ? bk : bv);
    float* out        = (z == 0) ? g_q : (z == 1 ? g_k : g_v);
    const float scale = (z == 0) ? QK_SCALE : 1.0f;

    __shared__ float AsT[64 * 66];   // [k][m] transposed, pad 66
    __shared__ float Bs[64 * 68];    // [k][n]

    const int t = threadIdx.x;
    const int tr = (t >> 4) * 4;     // m base (pairs tr..tr+3)
    const int tc = (t & 15) * 4;     // n base
    const int rowBase = blockIdx.y * 64;
    const int colBase = blockIdx.x * 64;

    ull acc2[2][4];
#pragma unroll
    for (int p = 0; p < 2; p++)
#pragma unroll
        for (int j = 0; j < 4; j++) acc2[p][j] = 0ull;

    for (int k0 = 0; k0 < DD; k0 += 64) {
        for (int i = t; i < 1024; i += 256) {
            int m = i >> 4, k4 = (i & 15) * 4;
            float4 x = *(const float4*)(X + (rowBase + m) * DD + k0 + k4);
            AsT[(k4 + 0) * 66 + m] = x.x;
            AsT[(k4 + 1) * 66 + m] = x.y;
            AsT[(k4 + 2) * 66 + m] = x.z;
            AsT[(k4 + 3) * 66 + m] = x.w;
        }
        for (int i = t; i < 1024; i += 256) {
            int k = i >> 4, n4 = (i & 15) * 4;
            *(float4*)(Bs + k * 68 + n4) = *(const float4*)(W + (k0 + k) * DD + colBase + n4);
        }
        __syncthreads();
#pragma unroll 16
        for (int kk = 0; kk < 64; kk++) {
            ull a0 = *(const ull*)(AsT + kk * 66 + tr);
            ull a1 = *(const ull*)(AsT + kk * 66 + tr + 2);
            float4 b4 = *(const float4*)(Bs + kk * 68 + tc);
            ull b0 = pack2(b4.x, b4.x);
            ull b1 = pack2(b4.y, b4.y);
            ull b2 = pack2(b4.z, b4.z);
            ull b3 = pack2(b4.w, b4.w);
            acc2[0][0] = fma2(a0, b0, acc2[0][0]);
            acc2[0][1] = fma2(a0, b1, acc2[0][1]);
            acc2[0][2] = fma2(a0, b2, acc2[0][2]);
            acc2[0][3] = fma2(a0, b3, acc2[0][3]);
            acc2[1][0] = fma2(a1, b0, acc2[1][0]);
            acc2[1][1] = fma2(a1, b1, acc2[1][1]);
            acc2[1][2] = fma2(a1, b2, acc2[1][2]);
            acc2[1][3] = fma2(a1, b3, acc2[1][3]);
        }
        __syncthreads();
    }

    const int col0 = colBase + tc;
    const int h = col0 >> 5, d = col0 & 31;
    const float4 bi = *(const float4*)(bias + col0);
#pragma unroll
    for (int p = 0; p < 2; p++) {
        float2 c0 = unpack2(acc2[p][0]);
        float2 c1 = unpack2(acc2[p][1]);
        float2 c2 = unpack2(acc2[p][2]);
        float2 c3 = unpack2(acc2[p][3]);
#pragma unroll
        for (int s = 0; s < 2; s++) {
            int row = rowBase + tr + p * 2 + s;
            int b = row >> 9, l = row & 511;
            float4 o;
            o.x = ((s ? c0.y : c0.x) + bi.x) * scale;
            o.y = ((s ? c1.y : c1.x) + bi.y) * scale;
            o.z = ((s ? c2.y : c2.x) + bi.z) * scale;
            o.w = ((s ? c3.y : c3.x) + bi.w) * scale;
            *(float4*)(out + (((b * HH + h) * LL) + l) * DH + d) = o;
        }
    }
}

// ---------------- kernel 2: fully fused attention ----------------
// per block: one bh, 32 q rows. P precompute + scores + softmax + attn write + ctx.
__global__ __launch_bounds__(256, 2) void attn_kernel(
        const float* __restrict__ uvec,
        const float* __restrict__ vvec,
        const float* __restrict__ rel_table,
        float* __restrict__ attn) {
    extern __shared__ float sm[];
    float* S    = sm;                  // [32][516] scores/exp
    float* KV   = S + 32 * 516;        // 8320 floats: KsT[32][260] or Vs[128][36] or tbl
    float* qu   = KV + 8320;           // [32][33]
    float* Ps   = qu + 32 * 33;        // [32][16]
    float* invp = Ps + 32 * 16;        // [32]

    const int bh = blockIdx.y;
    const int b = bh >> 3, h = bh & 7;
    const int q0 = blockIdx.x * 32;
    const int t = threadIdx.x;

    // -------- phase 0: qu = q+v, table slice, P --------
    {
        int q = t >> 3, d4 = (t & 7) * 4;
        float4 qv = *(const float4*)(g_q + ((size_t)bh * LL + q0 + q) * DH + d4);
        float4 vv = *(const float4*)(vvec + h * DH + d4);
        qu[q * 33 + d4 + 0] = qv.x + vv.x;
        qu[q * 33 + d4 + 1] = qv.y + vv.y;
        qu[q * 33 + d4 + 2] = qv.z + vv.z;
        qu[q * 33 + d4 + 3] = qv.w + vv.w;
    }
    float* tbl = KV;   // [12][33]
    for (int i = t; i < 384; i += 256) {
        int bu = i >> 5, d = i & 31;
        tbl[bu * 33 + d] = rel_table[bu * DD + h * DH + d];
    }
    __syncthreads();
    for (int j = t; j < 384; j += 256) {
        int q = j / 12, bu = j - q * 12;
        const float* qp = qu + q * 33;
        const float* tp = tbl + bu * 33;
        float s = 0.0f;
#pragma unroll
        for (int d = 0; d < 32; d++) s = fmaf(qp[d], tp[d], s);
        Ps[q * 16 + bu] = s;
    }
    if (t < 32) Ps[t * 16 + 12] = -1e18f;
    __syncthreads();
    // qu: (q+v) -> (q+u)
    {
        int q = t >> 3, d4 = (t & 7) * 4;
        float4 uu = *(const float4*)(uvec + h * DH + d4);
        float4 vv = *(const float4*)(vvec + h * DH + d4);
        qu[q * 33 + d4 + 0] += uu.x - vv.x;
        qu[q * 33 + d4 + 1] += uu.y - vv.y;
        qu[q * 33 + d4 + 2] += uu.z - vv.z;
        qu[q * 33 + d4 + 3] += uu.w - vv.w;
    }

    // -------- phase 1: scores (f32x2, pairs over k) --------
    const int tq = (t >> 5) * 4;       // warp-uniform q base
    const int tc2 = t & 31;            // k-pair lane

    for (int kc = 0; kc < LL; kc += 256) {
        __syncthreads();
        // load K chunk transposed: KsT[d][k], stride 260
        for (int i = t; i < 2048; i += 256) {
            int k = i >> 3, d4 = (i & 7) * 4;
            float4 kv = *(const float4*)(g_k + ((size_t)bh * LL + kc + k) * DH + d4);
            KV[(d4 + 0) * 260 + k] = kv.x;
            KV[(d4 + 1) * 260 + k] = kv.y;
            KV[(d4 + 2) * 260 + k] = kv.z;
            KV[(d4 + 3) * 260 + k] = kv.w;
        }
        __syncthreads();

        ull acc2[4][4];
#pragma unroll
        for (int i = 0; i < 4; i++)
#pragma unroll
            for (int j = 0; j < 4; j++) acc2[i][j] = 0ull;

#pragma unroll
        for (int d = 0; d < DH; d++) {
            ull a2[4];
#pragma unroll
            for (int i = 0; i < 4; i++) {
                float a = qu[(tq + i) * 33 + d];
                a2[i] = pack2(a, a);
            }
            const float* Kd = KV + d * 260 + 2 * tc2;
#pragma unroll
            for (int j = 0; j < 4; j++) {
                ull b2 = *(const ull*)(Kd + 64 * j);
                acc2[0][j] = fma2(a2[0], b2, acc2[0][j]);
                acc2[1][j] = fma2(a2[1], b2, acc2[1][j]);
                acc2[2][j] = fma2(a2[2], b2, acc2[2][j]);
                acc2[3][j] = fma2(a2[3], b2, acc2[3][j]);
            }
        }

        // epilogue: add P[idx], store raw scores into S
#pragma unroll
        for (int i = 0; i < 4; i++) {
            int q = tq + i;
            const unsigned char* ip = g_idx + ((size_t)(b * LL + q0 + q)) * LL + kc + 2 * tc2;
            const float* Pq = Ps + q * 16;
            float* Sr = S + q * 516 + kc + 2 * tc2;
#pragma unroll
            for (int j = 0; j < 4; j++) {
                unsigned int u2 = *(const unsigned short*)(ip + 64 * j);
                float2 s2 = unpack2(acc2[i][j]);
                float2 o;
                o.x = s2.x + Pq[u2 & 255];
                o.y = s2.y + Pq[(u2 >> 8) & 255];
                *(float2*)(Sr + 64 * j) = o;
            }
        }
    }
    __syncthreads();

    // -------- phase 2: softmax rows, write normalized attn --------
    {
        const int w = t >> 5, lane = t & 31;
#pragma unroll
        for (int rr = 0; rr < 4; rr++) {
            int r = w * 4 + rr;
            float* Sr = S + r * 516;
            float m = -3.4e38f;
            for (int c = lane; c < LL; c += 32) m = fmaxf(m, Sr[c]);
#pragma unroll
            for (int o = 16; o; o >>= 1) m = fmaxf(m, __shfl_xor_sync(0xffffffffu, m, o));
            float s = 0.0f;
            for (int c = lane; c < LL; c += 32) {
                float e = __expf(Sr[c] - m);
                Sr[c] = e;
                s += e;
            }
#pragma unroll
            for (int o = 16; o; o >>= 1) s += __shfl_xor_sync(0xffffffffu, s, o);
            if (lane == 0) invp[r] = 1.0f / s;
        }
    }
    __syncthreads();

    float* arow = attn + ((size_t)(bh * LL + q0)) * LL;
    for (int i = t; i < 32 * 128; i += 256) {
        int r = i >> 7, c4 = (i & 127) << 2;
        float iv = invp[r];
        float4 e = *(const float4*)(S + r * 516 + c4);
        float4 o = make_float4(e.x * iv, e.y * iv, e.z * iv, e.w * iv);
        *(float4*)(arow + r * LL + c4) = o;
    }

    // -------- phase 3: ctx = S @ V (f32x2, pairs over d) --------
    const int qq = t >> 3;
    const int d4 = (t & 7) * 4;
    ull acc0 = 0ull, acc1 = 0ull;

    for (int kc = 0; kc < LL; kc += 128) {
        __syncthreads();
        for (int i = t; i < 1024; i += 256) {
            int k = i >> 3, dd = (i & 7) * 4;
            *(float4*)(KV + k * 36 + dd) =
                *(const float4*)(g_v + ((size_t)bh * LL + kc + k) * DH + dd);
        }
        __syncthreads();
        const float* Sq = S + qq * 516 + kc;
#pragma unroll 8
        for (int kk = 0; kk < 128; kk++) {
            float a = Sq[kk];
            ull a2 = pack2(a, a);
            const float* Vr = KV + kk * 36 + d4;
            acc0 = fma2(a2, *(const ull*)(Vr), acc0);
            acc1 = fma2(a2, *(const ull*)(Vr + 2), acc1);
        }
    }
    const float iv = invp[qq];
    float2 c0 = unpack2(acc0), c1 = unpack2(acc1);
    float4 o = make_float4(c0.x * iv, c0.y * iv, c1.x * iv, c1.y * iv);
    *(float4*)(g_ctx + ((size_t)(b * LL) + q0 + qq) * DD + h * DH + d4) = o;
}

// ---------------- kernel 3: output GEMM ctx @ Wo + bo (f32x2) ----------------
__global__ __launch_bounds__(256) void out_gemm_kernel(
        const float* __restrict__ Wo,
        const float* __restrict__ bo,
        float* __restrict__ out) {
    __shared__ float AsT[64 * 66];
    __shared__ float Bs[64 * 68];

    const int t = threadIdx.x;
    const int tr = (t >> 4) * 4;
    const int tc = (t & 15) * 4;
    const int rowBase = blockIdx.y * 64;
    const int colBase = blockIdx.x * 64;

    ull acc2[2][4];
#pragma unroll
    for (int p = 0; p < 2; p++)
#pragma unroll
        for (int j = 0; j < 4; j++) acc2[p][j] = 0ull;

    for (int k0 = 0; k0 < DD; k0 += 64) {
        for (int i = t; i < 1024; i += 256) {
            int m = i >> 4, k4 = (i & 15) * 4;
            float4 x = *(const float4*)(g_ctx + (rowBase + m) * DD + k0 + k4);
            AsT[(k4 + 0) * 66 + m] = x.x;
            AsT[(k4 + 1) * 66 + m] = x.y;
            AsT[(k4 + 2) * 66 + m] = x.z;
            AsT[(k4 + 3) * 66 + m] = x.w;
        }
        for (int i = t; i < 1024; i += 256) {
            int k = i >> 4, n4 = (i & 15) * 4;
            *(float4*)(Bs + k * 68 + n4) = *(const float4*)(Wo + (k0 + k) * DD + colBase + n4);
        }
        __syncthreads();
#pragma unroll 16
        for (int kk = 0; kk < 64; kk++) {
            ull a0 = *(const ull*)(AsT + kk * 66 + tr);
            ull a1 = *(const ull*)(AsT + kk * 66 + tr + 2);
            float4 b4 = *(const float4*)(Bs + kk * 68 + tc);
            ull b0 = pack2(b4.x, b4.x);
            ull b1 = pack2(b4.y, b4.y);
            ull b2 = pack2(b4.z, b4.z);
            ull b3 = pack2(b4.w, b4.w);
            acc2[0][0] = fma2(a0, b0, acc2[0][0]);
            acc2[0][1] = fma2(a0, b1, acc2[0][1]);
            acc2[0][2] = fma2(a0, b2, acc2[0][2]);
            acc2[0][3] = fma2(a0, b3, acc2[0][3]);
            acc2[1][0] = fma2(a1, b0, acc2[1][0]);
            acc2[1][1] = fma2(a1, b1, acc2[1][1]);
            acc2[1][2] = fma2(a1, b2, acc2[1][2]);
            acc2[1][3] = fma2(a1, b3, acc2[1][3]);
        }
        __syncthreads();
    }

    const int col0 = colBase + tc;
    const float4 bi = *(const float4*)(bo + col0);
#pragma unroll
    for (int p = 0; p < 2; p++) {
        float2 c0 = unpack2(acc2[p][0]);
        float2 c1 = unpack2(acc2[p][1]);
        float2 c2 = unpack2(acc2[p][2]);
        float2 c3 = unpack2(acc2[p][3]);
#pragma unroll
        for (int s = 0; s < 2; s++) {
            int row = rowBase + tr + p * 2 + s;
            float4 o;
            o.x = (s ? c0.y : c0.x) + bi.x;
            o.y = (s ? c1.y : c1.x) + bi.y;
            o.z = (s ? c2.y : c2.x) + bi.z;
            o.w = (s ? c3.y : c3.x) + bi.w;
            *(float4*)(out + row * DD + col0) = o;
        }
    }
}

// ---------------- launch ----------------
extern "C" void kernel_launch(void* const* d_in, const int* in_sizes, int n_in,
                              void* d_out, int out_size) {
    const float* X         = (const float*)d_in[0];
    const void*  mask      = d_in[1];
    const int*   distances = (const int*)d_in[2];
    const float* Wq        = (const float*)d_in[3];
    const float* bq        = (const float*)d_in[4];
    const float* Wk        = (const float*)d_in[5];
    const float* bk        = (const float*)d_in[6];
    const float* Wv        = (const float*)d_in[7];
    const float* bv        = (const float*)d_in[8];
    const float* Wo        = (const float*)d_in[9];
    const float* bo        = (const float*)d_in[10];
    const float* rel_table = (const float*)d_in[11];
    const float* uvec      = (const float*)d_in[12];
    const float* vvec      = (const float*)d_in[13];

    float* out  = (float*)d_out;                       // (B,L,D)
    float* attn = (float*)d_out + BB * LL * DD;        // (B,H,L,L)

    const int attn_smem = (32 * 516 + 8320 + 32 * 33 + 32 * 16 + 32) * 4;
    static int smem_set = 0;
    if (!smem_set) {
        cudaFuncSetAttribute(attn_kernel,
                             cudaFuncAttributeMaxDynamicSharedMemorySize,
                             attn_smem);
        smem_set = 1;
    }

    detect_mask_kernel<<<1, 256>>>((const unsigned int*)mask);
    prep_idx_kernel<<<1024, 256>>>(mask, distances);
    qkv_gemm_kernel<<<dim3(4, 32, 3), 256>>>(X, Wq, bq, Wk, bk, Wv, bv);
    attn_kernel<<<dim3(16, 32), 256, attn_smem>>>(uvec, vvec, rel_table, attn);
    out_gemm_kernel<<<dim3(4, 32), 256>>>(Wo, bo, out);
}